// round 5
// baseline (speedup 1.0000x reference)
#include <cuda_runtime.h>

#define NB 16
#define CH 256
#define KS 6
#define MS 22
#define HO 17
#define OUT_PER_N (HO*HO)          // 289
#define TOT_OUT (NB*OUT_PER_N)     // 4624
#define CPB 16                     // channels per block
#define NCHUNK (CH/CPB)            // 16
#define RS 23                      // padded smem row stride (odd -> conflict-free LDS)
#define CSTR (MS*RS)               // 506 floats per channel tile
#define TPB 272                    // 17 oy * 16 cl
#define NS 3                       // ox splits: widths 6,6,5
#define OXW 6                      // max outputs per thread
#define XCOLS 11                   // x columns per row per split
#define IDX4 (TOT_OUT/4)           // 1156 float4 columns

// partials: [chunk][idx], 16B-aligned for float4 epilogue reads
__device__ float4 g_p4[NCHUNK * IDX4];

__device__ __forceinline__ float fsqrt_fast(float a) {
    float r; asm("sqrt.approx.f32 %0, %1;" : "=f"(r) : "f"(a)); return r;
}

// ---------------------------------------------------------------------------
// Kernel 1: per-(chunk, n, ox-split) sliding correlation.
// thread = (oy, channel lane); 6 (or 5) sliding outputs.
// ---------------------------------------------------------------------------
__global__ __launch_bounds__(TPB, 5) void corr_kernel(
    const float* __restrict__ z, const float* __restrict__ x,
    const float* __restrict__ w)
{
    __shared__ float xs[CPB * CSTR];      // 8096 floats; reused as reduce scratch
    __shared__ float zs[CPB * KS * KS];   // 576

    const int chunk = blockIdx.x;
    const int n     = blockIdx.y;
    const int s     = blockIdx.z;
    const int ox0   = s * OXW;            // 0, 6, 12
    const int t     = threadIdx.x;

    // --- x load: float4 gmem, fused sqrt ---
    // 484 floats/ch = 121 float4; wrap over the 22-wide row only when c0==20,
    // and then elements 2,3 shift by exactly +1 (RS-MS == 1).
    const float4* xg4 = (const float4*)(x + (size_t)(n * CH + chunk * CPB) * (MS * MS));
    for (int e4 = t; e4 < CPB * 121; e4 += TPB) {
        float4 v = xg4[e4];
        unsigned cl   = (unsigned)e4 / 121u;
        unsigned rem4 = (unsigned)e4 - cl * 121u;
        unsigned r0   = (2u * rem4) / 11u;            // (4*rem4)/22
        unsigned c0   = 4u * rem4 - 22u * r0;         // even, 0..20
        unsigned base = cl * CSTR + r0 * RS + c0;
        unsigned p    = (c0 == 20u) ? 1u : 0u;
        xs[base + 0]     = fsqrt_fast(v.x);
        xs[base + 1]     = fsqrt_fast(v.y);
        xs[base + 2 + p] = fsqrt_fast(v.z);
        xs[base + 3 + p] = fsqrt_fast(v.w);
    }
    const float* zg = z + (size_t)(n * CH + chunk * CPB) * (KS * KS);
    for (int e = t; e < CPB * KS * KS; e += TPB) {
        unsigned cl = (unsigned)e / 36u;
        zs[e] = fsqrt_fast(zg[e]) * w[chunk * CPB + cl];
    }
    __syncthreads();

    // --- compute: thread = (oy, cl); 6 sliding outputs (s==2: 5 valid) ---
    const int oy = t % HO;
    const int cl = t / HO;
    const float* xb = &xs[cl * CSTR + ox0];
    const float* zb = &zs[cl * KS * KS];

    float acc[OXW];
#pragma unroll
    for (int i = 0; i < OXW; i++) acc[i] = 0.f;

#pragma unroll
    for (int k1 = 0; k1 < KS; k1++) {
        float xr[XCOLS];
#pragma unroll
        for (int j = 0; j < XCOLS; j++) xr[j] = xb[(oy + k1) * RS + j];
#pragma unroll
        for (int k2 = 0; k2 < KS; k2++) {
            float zv = zb[k1 * KS + k2];
#pragma unroll
            for (int i = 0; i < OXW; i++)
                acc[i] = fmaf(xr[i + k2], zv, acc[i]);
        }
    }

    // --- block reduce over 16 channel lanes (fixed order -> deterministic) ---
    __syncthreads();
    float* scratch = xs;                  // 16 * 102 floats
#pragma unroll
    for (int i = 0; i < OXW; i++)
        scratch[cl * (HO * OXW) + oy * OXW + i] = acc[i];
    __syncthreads();

    float* gp = (float*)g_p4;             // [chunk][4624]
    for (int idx = t; idx < HO * OXW; idx += TPB) {
        int oyo = idx / OXW;
        int i   = idx - oyo * OXW;
        if (s == 2 && i == OXW - 1) continue;      // split 2 has only 5 outputs
        float v = 0.f;
#pragma unroll
        for (int c2 = 0; c2 < CPB; c2++) v += scratch[c2 * (HO * OXW) + idx];
        gp[chunk * TOT_OUT + n * OUT_PER_N + oyo * HO + ox0 + i] = v;
    }
}

// ---------------------------------------------------------------------------
// Kernel 2: chunk reduce (coalesced float4 columns) + global BatchNorm.
// Thread t owns idx4 = t (and 1024+t for t<132): 4 consecutive outputs each.
// ---------------------------------------------------------------------------
#define BNT 1024
__global__ __launch_bounds__(BNT) void reduce_bn(
    float* __restrict__ out,
    const float* __restrict__ bw, const float* __restrict__ bb)
{
    __shared__ float sred[BNT];
    __shared__ float s_mu, s_scale;
    const int t = threadIdx.x;

    float v[8];
    int own2 = (t < IDX4 - BNT);          // second column group?
    float lsum = 0.f;
#pragma unroll
    for (int g = 0; g < 2; g++) {
        int idx4 = t + g * BNT;
        float4 a = make_float4(0.f, 0.f, 0.f, 0.f);
        if (g == 0 || own2) {
#pragma unroll
            for (int ch = 0; ch < NCHUNK; ch++) {
                float4 p = g_p4[ch * IDX4 + idx4];
                a.x += p.x; a.y += p.y; a.z += p.z; a.w += p.w;
            }
            a.x *= (1.f/36.f); a.y *= (1.f/36.f); a.z *= (1.f/36.f); a.w *= (1.f/36.f);
        }
        v[g*4+0] = a.x; v[g*4+1] = a.y; v[g*4+2] = a.z; v[g*4+3] = a.w;
        lsum += (a.x + a.y) + (a.z + a.w);
    }

    sred[t] = lsum; __syncthreads();
    for (int sz = BNT / 2; sz > 0; sz >>= 1) { if (t < sz) sred[t] += sred[t + sz]; __syncthreads(); }
    if (t == 0) s_mu = sred[0] / (float)TOT_OUT;
    __syncthreads();
    const float mu = s_mu;

    float lss = 0.f;
#pragma unroll
    for (int g = 0; g < 2; g++) {
        if (g == 1 && !own2) break;
#pragma unroll
        for (int j = 0; j < 4; j++) { float d = v[g*4+j] - mu; lss += d * d; }
    }
    sred[t] = lss; __syncthreads();
    for (int sz = BNT / 2; sz > 0; sz >>= 1) { if (t < sz) sred[t] += sred[t + sz]; __syncthreads(); }
    if (t == 0) s_scale = rsqrtf(sred[0] / (float)TOT_OUT + 1e-5f) * bw[0];
    __syncthreads();
    const float scale = s_scale;
    const float bias  = bb[0];

#pragma unroll
    for (int g = 0; g < 2; g++) {
        if (g == 1 && !own2) break;
        int idx4 = t + g * BNT;
        float4 o;
        o.x = (v[g*4+0] - mu) * scale + bias;
        o.y = (v[g*4+1] - mu) * scale + bias;
        o.z = (v[g*4+2] - mu) * scale + bias;
        o.w = (v[g*4+3] - mu) * scale + bias;
        ((float4*)out)[idx4] = o;
    }
}

extern "C" void kernel_launch(void* const* d_in, const int* in_sizes, int n_in,
                              void* d_out, int out_size)
{
    const float* z  = (const float*)d_in[0];
    const float* x  = (const float*)d_in[1];
    const float* w  = (const float*)d_in[2];
    const float* bw = (const float*)d_in[3];
    const float* bb = (const float*)d_in[4];

    int first_one = -1;
    for (int i = 0; i < n_in; i++) {
        if (in_sizes[i] == NB * CH * KS * KS)      z = (const float*)d_in[i];
        else if (in_sizes[i] == NB * CH * MS * MS) x = (const float*)d_in[i];
        else if (in_sizes[i] == CH)                w = (const float*)d_in[i];
        else if (in_sizes[i] == 1) {
            if (first_one < 0) { bw = (const float*)d_in[i]; first_one = i; }
            else                 bb = (const float*)d_in[i];
        }
    }

    dim3 grid(NCHUNK, NB, NS);                   // 16 x 16 x 3 = 768 blocks
    corr_kernel<<<grid, TPB>>>(z, x, w);
    reduce_bn<<<1, BNT>>>((float*)d_out, bw, bb);
}

// round 6
// speedup vs baseline: 1.0091x; 1.0091x over previous
#include <cuda_runtime.h>

#define NB 16
#define CH 256
#define KS 6
#define MS 22
#define HO 17
#define OUT_PER_N (HO*HO)          // 289
#define TOT_OUT (NB*OUT_PER_N)     // 4624
#define CPB 16                     // channels per block
#define NCHUNK (CH/CPB)            // 16
#define RS 23                      // padded smem row stride (odd -> conflict-free LDS)
#define CSTR (MS*RS)               // 506 floats per channel tile
#define TPB 272                    // 17 oy * 16 cl
#define NS 3                       // ox splits: widths 6,6,5
#define OXW 6                      // max outputs per thread
#define XCOLS 11                   // x columns per row per split
#define IDX4 (TOT_OUT/4)           // 1156 float4 columns

// partials: [chunk][idx], 16B-aligned for float4 epilogue reads
__device__ float4 g_p4[NCHUNK * IDX4];

__device__ __forceinline__ float fsqrt_fast(float a) {
    float r; asm("sqrt.approx.f32 %0, %1;" : "=f"(r) : "f"(a)); return r;
}

// ---------------------------------------------------------------------------
// Kernel 1: per-(chunk, n, ox-split) sliding correlation. (unchanged from R5)
// ---------------------------------------------------------------------------
__global__ __launch_bounds__(TPB, 5) void corr_kernel(
    const float* __restrict__ z, const float* __restrict__ x,
    const float* __restrict__ w)
{
    __shared__ float xs[CPB * CSTR];      // 8096 floats; reused as reduce scratch
    __shared__ float zs[CPB * KS * KS];   // 576

    const int chunk = blockIdx.x;
    const int n     = blockIdx.y;
    const int s     = blockIdx.z;
    const int ox0   = s * OXW;            // 0, 6, 12
    const int t     = threadIdx.x;

    const float4* xg4 = (const float4*)(x + (size_t)(n * CH + chunk * CPB) * (MS * MS));
    for (int e4 = t; e4 < CPB * 121; e4 += TPB) {
        float4 v = xg4[e4];
        unsigned cl   = (unsigned)e4 / 121u;
        unsigned rem4 = (unsigned)e4 - cl * 121u;
        unsigned r0   = (2u * rem4) / 11u;            // (4*rem4)/22
        unsigned c0   = 4u * rem4 - 22u * r0;         // even, 0..20
        unsigned base = cl * CSTR + r0 * RS + c0;
        unsigned p    = (c0 == 20u) ? 1u : 0u;        // row-wrap shifts exactly +1
        xs[base + 0]     = fsqrt_fast(v.x);
        xs[base + 1]     = fsqrt_fast(v.y);
        xs[base + 2 + p] = fsqrt_fast(v.z);
        xs[base + 3 + p] = fsqrt_fast(v.w);
    }
    const float* zg = z + (size_t)(n * CH + chunk * CPB) * (KS * KS);
    for (int e = t; e < CPB * KS * KS; e += TPB) {
        unsigned cl = (unsigned)e / 36u;
        zs[e] = fsqrt_fast(zg[e]) * w[chunk * CPB + cl];
    }
    __syncthreads();

    const int oy = t % HO;
    const int cl = t / HO;
    const float* xb = &xs[cl * CSTR + ox0];
    const float* zb = &zs[cl * KS * KS];

    float acc[OXW];
#pragma unroll
    for (int i = 0; i < OXW; i++) acc[i] = 0.f;

#pragma unroll
    for (int k1 = 0; k1 < KS; k1++) {
        float xr[XCOLS];
#pragma unroll
        for (int j = 0; j < XCOLS; j++) xr[j] = xb[(oy + k1) * RS + j];
#pragma unroll
        for (int k2 = 0; k2 < KS; k2++) {
            float zv = zb[k1 * KS + k2];
#pragma unroll
            for (int i = 0; i < OXW; i++)
                acc[i] = fmaf(xr[i + k2], zv, acc[i]);
        }
    }

    __syncthreads();
    float* scratch = xs;                  // 16 * 102 floats
#pragma unroll
    for (int i = 0; i < OXW; i++)
        scratch[cl * (HO * OXW) + oy * OXW + i] = acc[i];
    __syncthreads();

    float* gp = (float*)g_p4;             // [chunk][4624]
    for (int idx = t; idx < HO * OXW; idx += TPB) {
        int oyo = idx / OXW;
        int i   = idx - oyo * OXW;
        if (s == 2 && i == OXW - 1) continue;      // split 2 has only 5 outputs
        float v = 0.f;
#pragma unroll
        for (int c2 = 0; c2 < CPB; c2++) v += scratch[c2 * (HO * OXW) + idx];
        gp[chunk * TOT_OUT + n * OUT_PER_N + oyo * HO + ox0 + i] = v;
    }
}

// ---------------------------------------------------------------------------
// Kernel 2: chunk reduce + global BatchNorm.
// 512 threads (128-reg budget): per column, front-batch ALL 16 chunk loads
// into registers (MLP=16) before accumulating -> latency-hiding, not a
// serialized load-add chain.
// ---------------------------------------------------------------------------
#define BNT 512
#define NG 3                                // column groups: t, t+512, t+1024
__global__ __launch_bounds__(BNT) void reduce_bn(
    float* __restrict__ out,
    const float* __restrict__ bw, const float* __restrict__ bb)
{
    __shared__ float sred[BNT];
    __shared__ float s_mu, s_scale;
    const int t = threadIdx.x;
    const bool own3 = (t < IDX4 - 2 * BNT);   // 1156 - 1024 = 132

    float v[NG * 4];
    float lsum = 0.f;
#pragma unroll
    for (int g = 0; g < NG; g++) {
        int idx4 = t + g * BNT;
        float4 a = make_float4(0.f, 0.f, 0.f, 0.f);
        if (g < 2 || own3) {
            float4 p[NCHUNK];
#pragma unroll
            for (int ch = 0; ch < NCHUNK; ch++)          // 16 independent LDG.128
                p[ch] = g_p4[ch * IDX4 + idx4];
#pragma unroll
            for (int ch = 0; ch < NCHUNK; ch++) {        // fixed-order accumulate
                a.x += p[ch].x; a.y += p[ch].y; a.z += p[ch].z; a.w += p[ch].w;
            }
            a.x *= (1.f/36.f); a.y *= (1.f/36.f); a.z *= (1.f/36.f); a.w *= (1.f/36.f);
        }
        v[g*4+0] = a.x; v[g*4+1] = a.y; v[g*4+2] = a.z; v[g*4+3] = a.w;
        lsum += (a.x + a.y) + (a.z + a.w);
    }

    sred[t] = lsum; __syncthreads();
    for (int sz = BNT / 2; sz > 0; sz >>= 1) { if (t < sz) sred[t] += sred[t + sz]; __syncthreads(); }
    if (t == 0) s_mu = sred[0] / (float)TOT_OUT;
    __syncthreads();
    const float mu = s_mu;

    float lss = 0.f;
#pragma unroll
    for (int g = 0; g < NG; g++) {
        if (g == 2 && !own3) break;
#pragma unroll
        for (int j = 0; j < 4; j++) { float d = v[g*4+j] - mu; lss += d * d; }
    }
    sred[t] = lss; __syncthreads();
    for (int sz = BNT / 2; sz > 0; sz >>= 1) { if (t < sz) sred[t] += sred[t + sz]; __syncthreads(); }
    if (t == 0) s_scale = rsqrtf(sred[0] / (float)TOT_OUT + 1e-5f) * bw[0];
    __syncthreads();
    const float scale = s_scale;
    const float bias  = bb[0];

#pragma unroll
    for (int g = 0; g < NG; g++) {
        if (g == 2 && !own3) break;
        int idx4 = t + g * BNT;
        float4 o;
        o.x = (v[g*4+0] - mu) * scale + bias;
        o.y = (v[g*4+1] - mu) * scale + bias;
        o.z = (v[g*4+2] - mu) * scale + bias;
        o.w = (v[g*4+3] - mu) * scale + bias;
        ((float4*)out)[idx4] = o;
    }
}

extern "C" void kernel_launch(void* const* d_in, const int* in_sizes, int n_in,
                              void* d_out, int out_size)
{
    const float* z  = (const float*)d_in[0];
    const float* x  = (const float*)d_in[1];
    const float* w  = (const float*)d_in[2];
    const float* bw = (const float*)d_in[3];
    const float* bb = (const float*)d_in[4];

    int first_one = -1;
    for (int i = 0; i < n_in; i++) {
        if (in_sizes[i] == NB * CH * KS * KS)      z = (const float*)d_in[i];
        else if (in_sizes[i] == NB * CH * MS * MS) x = (const float*)d_in[i];
        else if (in_sizes[i] == CH)                w = (const float*)d_in[i];
        else if (in_sizes[i] == 1) {
            if (first_one < 0) { bw = (const float*)d_in[i]; first_one = i; }
            else                 bb = (const float*)d_in[i];
        }
    }

    dim3 grid(NCHUNK, NB, NS);                   // 16 x 16 x 3 = 768 blocks
    corr_kernel<<<grid, TPB>>>(z, x, w);
    reduce_bn<<<1, BNT>>>((float*)d_out, bw, bb);
}

// round 7
// speedup vs baseline: 1.0107x; 1.0015x over previous
#include <cuda_runtime.h>

#define NB 16
#define CH 256
#define KS 6
#define MS 22
#define HO 17
#define OUT_PER_N (HO*HO)          // 289
#define TOT_OUT (NB*OUT_PER_N)     // 4624
#define CPB 16                     // channels per block
#define NCHUNK (CH/CPB)            // 16
#define RS 23                      // padded smem row stride (odd -> conflict-free LDS)
#define CSTR (MS*RS)               // 506 floats per channel tile
#define TPB 272                    // 17 oy * 16 cl
#define NS 3                       // ox splits: widths 6,6,5
#define OXW 6                      // max outputs per thread
#define XCOLS 11                   // x columns per row per split
#define IDX4 (TOT_OUT/4)           // 1156 float4 columns

// partials: [chunk][idx], 16B-aligned
__device__ float4 g_p4[NCHUNK * IDX4];
__device__ float4 g_mean4[IDX4];            // mean_coeff

__device__ __forceinline__ float fsqrt_fast(float a) {
    float r; asm("sqrt.approx.f32 %0, %1;" : "=f"(r) : "f"(a)); return r;
}

// ---------------------------------------------------------------------------
// Kernel 1: per-(chunk, n, ox-split) sliding correlation. (unchanged)
// ---------------------------------------------------------------------------
__global__ __launch_bounds__(TPB, 5) void corr_kernel(
    const float* __restrict__ z, const float* __restrict__ x,
    const float* __restrict__ w)
{
    __shared__ float xs[CPB * CSTR];      // 8096 floats; reused as reduce scratch
    __shared__ float zs[CPB * KS * KS];   // 576

    const int chunk = blockIdx.x;
    const int n     = blockIdx.y;
    const int s     = blockIdx.z;
    const int ox0   = s * OXW;            // 0, 6, 12
    const int t     = threadIdx.x;

    const float4* xg4 = (const float4*)(x + (size_t)(n * CH + chunk * CPB) * (MS * MS));
    for (int e4 = t; e4 < CPB * 121; e4 += TPB) {
        float4 v = xg4[e4];
        unsigned cl   = (unsigned)e4 / 121u;
        unsigned rem4 = (unsigned)e4 - cl * 121u;
        unsigned r0   = (2u * rem4) / 11u;            // (4*rem4)/22
        unsigned c0   = 4u * rem4 - 22u * r0;         // even, 0..20
        unsigned base = cl * CSTR + r0 * RS + c0;
        unsigned p    = (c0 == 20u) ? 1u : 0u;        // row-wrap shifts exactly +1
        xs[base + 0]     = fsqrt_fast(v.x);
        xs[base + 1]     = fsqrt_fast(v.y);
        xs[base + 2 + p] = fsqrt_fast(v.z);
        xs[base + 3 + p] = fsqrt_fast(v.w);
    }
    const float* zg = z + (size_t)(n * CH + chunk * CPB) * (KS * KS);
    for (int e = t; e < CPB * KS * KS; e += TPB) {
        unsigned cl = (unsigned)e / 36u;
        zs[e] = fsqrt_fast(zg[e]) * w[chunk * CPB + cl];
    }
    __syncthreads();

    const int oy = t % HO;
    const int cl = t / HO;
    const float* xb = &xs[cl * CSTR + ox0];
    const float* zb = &zs[cl * KS * KS];

    float acc[OXW];
#pragma unroll
    for (int i = 0; i < OXW; i++) acc[i] = 0.f;

#pragma unroll
    for (int k1 = 0; k1 < KS; k1++) {
        float xr[XCOLS];
#pragma unroll
        for (int j = 0; j < XCOLS; j++) xr[j] = xb[(oy + k1) * RS + j];
#pragma unroll
        for (int k2 = 0; k2 < KS; k2++) {
            float zv = zb[k1 * KS + k2];
#pragma unroll
            for (int i = 0; i < OXW; i++)
                acc[i] = fmaf(xr[i + k2], zv, acc[i]);
        }
    }

    __syncthreads();
    float* scratch = xs;                  // 16 * 102 floats
#pragma unroll
    for (int i = 0; i < OXW; i++)
        scratch[cl * (HO * OXW) + oy * OXW + i] = acc[i];
    __syncthreads();

    float* gp = (float*)g_p4;             // [chunk][4624]
    for (int idx = t; idx < HO * OXW; idx += TPB) {
        int oyo = idx / OXW;
        int i   = idx - oyo * OXW;
        if (s == 2 && i == OXW - 1) continue;      // split 2 has only 5 outputs
        float v = 0.f;
#pragma unroll
        for (int c2 = 0; c2 < CPB; c2++) v += scratch[c2 * (HO * OXW) + idx];
        gp[chunk * TOT_OUT + n * OUT_PER_N + oyo * HO + ox0 + i] = v;
    }
}

// ---------------------------------------------------------------------------
// Kernel 2: chunk reduce spread over 10 blocks. One float4 column per thread;
// 16 chunk loads split into 4 independent accumulator chains (ILP=4), and
// latency overlapped across 40 warps / 10 SMs.
// ---------------------------------------------------------------------------
#define CRB 128
__global__ __launch_bounds__(CRB) void chunk_reduce()
{
    int idx4 = blockIdx.x * CRB + threadIdx.x;
    if (idx4 >= IDX4) return;

    float4 a0 = make_float4(0.f,0.f,0.f,0.f), a1 = a0, a2 = a0, a3 = a0;
#pragma unroll
    for (int ch = 0; ch < NCHUNK; ch += 4) {
        float4 p0 = g_p4[(ch + 0) * IDX4 + idx4];
        float4 p1 = g_p4[(ch + 1) * IDX4 + idx4];
        float4 p2 = g_p4[(ch + 2) * IDX4 + idx4];
        float4 p3 = g_p4[(ch + 3) * IDX4 + idx4];
        a0.x += p0.x; a0.y += p0.y; a0.z += p0.z; a0.w += p0.w;
        a1.x += p1.x; a1.y += p1.y; a1.z += p1.z; a1.w += p1.w;
        a2.x += p2.x; a2.y += p2.y; a2.z += p2.z; a2.w += p2.w;
        a3.x += p3.x; a3.y += p3.y; a3.z += p3.z; a3.w += p3.w;
    }
    float4 r;
    r.x = ((a0.x + a1.x) + (a2.x + a3.x)) * (1.f/36.f);
    r.y = ((a0.y + a1.y) + (a2.y + a3.y)) * (1.f/36.f);
    r.z = ((a0.z + a1.z) + (a2.z + a3.z)) * (1.f/36.f);
    r.w = ((a0.w + a1.w) + (a2.w + a3.w)) * (1.f/36.f);
    g_mean4[idx4] = r;
}

// ---------------------------------------------------------------------------
// Kernel 3: single-block BatchNorm over 4624 values (reads only 18.5 KB).
// ---------------------------------------------------------------------------
#define BNT 512
#define NG 3
__global__ __launch_bounds__(BNT) void finalize(
    float* __restrict__ out,
    const float* __restrict__ bw, const float* __restrict__ bb)
{
    __shared__ float sred[BNT];
    __shared__ float s_mu, s_scale;
    const int t = threadIdx.x;
    const bool own3 = (t < IDX4 - 2 * BNT);   // 1156 - 1024 = 132

    float4 v[NG];
    float lsum = 0.f;
#pragma unroll
    for (int g = 0; g < NG; g++) {
        float4 a = make_float4(0.f,0.f,0.f,0.f);
        if (g < 2 || own3) a = g_mean4[t + g * BNT];
        v[g] = a;
        lsum += (a.x + a.y) + (a.z + a.w);
    }

    sred[t] = lsum; __syncthreads();
    for (int sz = BNT / 2; sz > 0; sz >>= 1) { if (t < sz) sred[t] += sred[t + sz]; __syncthreads(); }
    if (t == 0) s_mu = sred[0] / (float)TOT_OUT;
    __syncthreads();
    const float mu = s_mu;

    float lss = 0.f;
#pragma unroll
    for (int g = 0; g < NG; g++) {
        if (g == 2 && !own3) break;
        float dx = v[g].x - mu, dy = v[g].y - mu, dz = v[g].z - mu, dw = v[g].w - mu;
        lss += (dx*dx + dy*dy) + (dz*dz + dw*dw);
    }
    sred[t] = lss; __syncthreads();
    for (int sz = BNT / 2; sz > 0; sz >>= 1) { if (t < sz) sred[t] += sred[t + sz]; __syncthreads(); }
    if (t == 0) s_scale = rsqrtf(sred[0] / (float)TOT_OUT + 1e-5f) * bw[0];
    __syncthreads();
    const float scale = s_scale;
    const float bias  = bb[0];

#pragma unroll
    for (int g = 0; g < NG; g++) {
        if (g == 2 && !own3) break;
        float4 o;
        o.x = (v[g].x - mu) * scale + bias;
        o.y = (v[g].y - mu) * scale + bias;
        o.z = (v[g].z - mu) * scale + bias;
        o.w = (v[g].w - mu) * scale + bias;
        ((float4*)out)[t + g * BNT] = o;
    }
}

extern "C" void kernel_launch(void* const* d_in, const int* in_sizes, int n_in,
                              void* d_out, int out_size)
{
    const float* z  = (const float*)d_in[0];
    const float* x  = (const float*)d_in[1];
    const float* w  = (const float*)d_in[2];
    const float* bw = (const float*)d_in[3];
    const float* bb = (const float*)d_in[4];

    int first_one = -1;
    for (int i = 0; i < n_in; i++) {
        if (in_sizes[i] == NB * CH * KS * KS)      z = (const float*)d_in[i];
        else if (in_sizes[i] == NB * CH * MS * MS) x = (const float*)d_in[i];
        else if (in_sizes[i] == CH)                w = (const float*)d_in[i];
        else if (in_sizes[i] == 1) {
            if (first_one < 0) { bw = (const float*)d_in[i]; first_one = i; }
            else                 bb = (const float*)d_in[i];
        }
    }

    dim3 grid(NCHUNK, NB, NS);                   // 768 blocks
    corr_kernel<<<grid, TPB>>>(z, x, w);
    chunk_reduce<<<(IDX4 + CRB - 1) / CRB, CRB>>>();   // 10 blocks
    finalize<<<1, BNT>>>((float*)d_out, bw, bb);
}

// round 8
// speedup vs baseline: 1.1201x; 1.1083x over previous
#include <cuda_runtime.h>

#define NB 16
#define CH 256
#define KS 6
#define MS 22
#define HO 17
#define OUT_PER_N (HO*HO)          // 289
#define TOT_OUT (NB*OUT_PER_N)     // 4624
#define CPB 16                     // channels per block
#define NCHUNK (CH/CPB)            // 16
#define RS 23                      // padded smem row stride (odd -> conflict-free LDS)
#define CSTR (MS*RS)               // 506 floats per channel tile
#define NPAIR 9                    // ceil(17/2) oy-pairs
#define TPB (NPAIR*CPB)            // 144 threads
#define IDX4 (TOT_OUT/4)           // 1156 float4 columns

// partials: [chunk][idx], 16B-aligned
__device__ float4 g_p4[NCHUNK * IDX4];
__device__ float4 g_mean4[IDX4];            // mean_coeff

__device__ __forceinline__ float fsqrt_fast(float a) {
    float r; asm("sqrt.approx.f32 %0, %1;" : "=f"(r) : "f"(a)); return r;
}

// ---------------------------------------------------------------------------
// Kernel 1: per-(chunk, n) sliding correlation.
// thread = (oy-pair, channel lane): 2x17 outputs, z taps in registers.
// 1224 FMA vs ~190 LDS per thread; latency hidden by 34 indep accumulators.
// ---------------------------------------------------------------------------
__global__ __launch_bounds__(TPB, 2) void corr_kernel(
    const float* __restrict__ z, const float* __restrict__ x,
    const float* __restrict__ w)
{
    __shared__ float xs[CPB * CSTR];      // 8096 floats; reused as reduce scratch
    __shared__ float zs[CPB * KS * KS];   // 576

    const int chunk = blockIdx.x;
    const int n     = blockIdx.y;
    const int t     = threadIdx.x;

    // --- x load: float4 gmem, fused sqrt, padded smem rows ---
    const float4* xg4 = (const float4*)(x + (size_t)(n * CH + chunk * CPB) * (MS * MS));
    for (int e4 = t; e4 < CPB * 121; e4 += TPB) {
        float4 v = xg4[e4];
        unsigned cl   = (unsigned)e4 / 121u;
        unsigned rem4 = (unsigned)e4 - cl * 121u;
        unsigned r0   = (2u * rem4) / 11u;            // (4*rem4)/22
        unsigned c0   = 4u * rem4 - 22u * r0;         // even, 0..20
        unsigned base = cl * CSTR + r0 * RS + c0;
        unsigned p    = (c0 == 20u) ? 1u : 0u;        // row-wrap shifts exactly +1
        xs[base + 0]     = fsqrt_fast(v.x);
        xs[base + 1]     = fsqrt_fast(v.y);
        xs[base + 2 + p] = fsqrt_fast(v.z);
        xs[base + 3 + p] = fsqrt_fast(v.w);
    }
    const float* zg = z + (size_t)(n * CH + chunk * CPB) * (KS * KS);
    for (int e = t; e < CPB * KS * KS; e += TPB) {
        unsigned cl = (unsigned)e / 36u;
        zs[e] = fsqrt_fast(zg[e]) * w[chunk * CPB + cl];
    }
    __syncthreads();

    // --- compute: thread = (oy-pair, channel); 2 output rows x 17 cols ---
    const int pair = t % NPAIR;
    const int cl   = t / NPAIR;
    const int oy0  = pair * 2;                 // 0,2,...,16 (pair 8: single row)
    const float* xb = &xs[cl * CSTR];

    float zr[KS * KS];
#pragma unroll
    for (int i = 0; i < KS * KS; i++) zr[i] = zs[cl * KS * KS + i];

    float a0[HO], a1[HO];
#pragma unroll
    for (int i = 0; i < HO; i++) { a0[i] = 0.f; a1[i] = 0.f; }

#pragma unroll
    for (int r = 0; r < 7; r++) {              // rows oy0 .. oy0+6
        int row = oy0 + r;
        if (row > MS - 1) row = MS - 1;        // pair 8, r==6: dummy (a1 unused)
        float xr[MS];
#pragma unroll
        for (int j = 0; j < MS; j++) xr[j] = xb[row * RS + j];
        if (r < 6) {                           // feeds out-row 0, tap k1=r
#pragma unroll
            for (int k2 = 0; k2 < KS; k2++) {
                float zv = zr[r * KS + k2];
#pragma unroll
                for (int ox = 0; ox < HO; ox++)
                    a0[ox] = fmaf(xr[ox + k2], zv, a0[ox]);
            }
        }
        if (r >= 1) {                          // feeds out-row 1, tap k1=r-1
#pragma unroll
            for (int k2 = 0; k2 < KS; k2++) {
                float zv = zr[(r - 1) * KS + k2];
#pragma unroll
                for (int ox = 0; ox < HO; ox++)
                    a1[ox] = fmaf(xr[ox + k2], zv, a1[ox]);
            }
        }
    }

    // --- block reduce over 16 channel lanes (fixed order -> deterministic) ---
    __syncthreads();
    float* scratch = xs;                       // 16 * 289 floats = 4624
#pragma unroll
    for (int ox = 0; ox < HO; ox++)
        scratch[cl * OUT_PER_N + oy0 * HO + ox] = a0[ox];
    if (pair < NPAIR - 1) {
#pragma unroll
        for (int ox = 0; ox < HO; ox++)
            scratch[cl * OUT_PER_N + (oy0 + 1) * HO + ox] = a1[ox];
    }
    __syncthreads();

    float* gp = (float*)g_p4;                  // [chunk][4624]
    for (int idx = t; idx < OUT_PER_N; idx += TPB) {
        float v = 0.f;
#pragma unroll
        for (int c2 = 0; c2 < CPB; c2++) v += scratch[c2 * OUT_PER_N + idx];
        gp[chunk * TOT_OUT + n * OUT_PER_N + idx] = v;
    }
}

// ---------------------------------------------------------------------------
// Kernel 2: chunk reduce spread over 10 blocks (4 indep accumulator chains).
// ---------------------------------------------------------------------------
#define CRB 128
__global__ __launch_bounds__(CRB) void chunk_reduce()
{
    int idx4 = blockIdx.x * CRB + threadIdx.x;
    if (idx4 >= IDX4) return;

    float4 a0 = make_float4(0.f,0.f,0.f,0.f), a1 = a0, a2 = a0, a3 = a0;
#pragma unroll
    for (int ch = 0; ch < NCHUNK; ch += 4) {
        float4 p0 = g_p4[(ch + 0) * IDX4 + idx4];
        float4 p1 = g_p4[(ch + 1) * IDX4 + idx4];
        float4 p2 = g_p4[(ch + 2) * IDX4 + idx4];
        float4 p3 = g_p4[(ch + 3) * IDX4 + idx4];
        a0.x += p0.x; a0.y += p0.y; a0.z += p0.z; a0.w += p0.w;
        a1.x += p1.x; a1.y += p1.y; a1.z += p1.z; a1.w += p1.w;
        a2.x += p2.x; a2.y += p2.y; a2.z += p2.z; a2.w += p2.w;
        a3.x += p3.x; a3.y += p3.y; a3.z += p3.z; a3.w += p3.w;
    }
    float4 r;
    r.x = ((a0.x + a1.x) + (a2.x + a3.x)) * (1.f/36.f);
    r.y = ((a0.y + a1.y) + (a2.y + a3.y)) * (1.f/36.f);
    r.z = ((a0.z + a1.z) + (a2.z + a3.z)) * (1.f/36.f);
    r.w = ((a0.w + a1.w) + (a2.w + a3.w)) * (1.f/36.f);
    g_mean4[idx4] = r;
}

// ---------------------------------------------------------------------------
// Kernel 3: single-block BatchNorm over 4624 values (reads only 18.5 KB).
// ---------------------------------------------------------------------------
#define BNT 512
#define NG 3
__global__ __launch_bounds__(BNT) void finalize(
    float* __restrict__ out,
    const float* __restrict__ bw, const float* __restrict__ bb)
{
    __shared__ float sred[BNT];
    __shared__ float s_mu, s_scale;
    const int t = threadIdx.x;
    const bool own3 = (t < IDX4 - 2 * BNT);   // 1156 - 1024 = 132

    float4 v[NG];
    float lsum = 0.f;
#pragma unroll
    for (int g = 0; g < NG; g++) {
        float4 a = make_float4(0.f,0.f,0.f,0.f);
        if (g < 2 || own3) a = g_mean4[t + g * BNT];
        v[g] = a;
        lsum += (a.x + a.y) + (a.z + a.w);
    }

    sred[t] = lsum; __syncthreads();
    for (int sz = BNT / 2; sz > 0; sz >>= 1) { if (t < sz) sred[t] += sred[t + sz]; __syncthreads(); }
    if (t == 0) s_mu = sred[0] / (float)TOT_OUT;
    __syncthreads();
    const float mu = s_mu;

    float lss = 0.f;
#pragma unroll
    for (int g = 0; g < NG; g++) {
        if (g == 2 && !own3) break;
        float dx = v[g].x - mu, dy = v[g].y - mu, dz = v[g].z - mu, dw = v[g].w - mu;
        lss += (dx*dx + dy*dy) + (dz*dz + dw*dw);
    }
    sred[t] = lss; __syncthreads();
    for (int sz = BNT / 2; sz > 0; sz >>= 1) { if (t < sz) sred[t] += sred[t + sz]; __syncthreads(); }
    if (t == 0) s_scale = rsqrtf(sred[0] / (float)TOT_OUT + 1e-5f) * bw[0];
    __syncthreads();
    const float scale = s_scale;
    const float bias  = bb[0];

#pragma unroll
    for (int g = 0; g < NG; g++) {
        if (g == 2 && !own3) break;
        float4 o;
        o.x = (v[g].x - mu) * scale + bias;
        o.y = (v[g].y - mu) * scale + bias;
        o.z = (v[g].z - mu) * scale + bias;
        o.w = (v[g].w - mu) * scale + bias;
        ((float4*)out)[t + g * BNT] = o;
    }
}

extern "C" void kernel_launch(void* const* d_in, const int* in_sizes, int n_in,
                              void* d_out, int out_size)
{
    const float* z  = (const float*)d_in[0];
    const float* x  = (const float*)d_in[1];
    const float* w  = (const float*)d_in[2];
    const float* bw = (const float*)d_in[3];
    const float* bb = (const float*)d_in[4];

    int first_one = -1;
    for (int i = 0; i < n_in; i++) {
        if (in_sizes[i] == NB * CH * KS * KS)      z = (const float*)d_in[i];
        else if (in_sizes[i] == NB * CH * MS * MS) x = (const float*)d_in[i];
        else if (in_sizes[i] == CH)                w = (const float*)d_in[i];
        else if (in_sizes[i] == 1) {
            if (first_one < 0) { bw = (const float*)d_in[i]; first_one = i; }
            else                 bb = (const float*)d_in[i];
        }
    }

    dim3 grid(NCHUNK, NB);                       // 256 blocks x 144 threads
    corr_kernel<<<grid, TPB>>>(z, x, w);
    chunk_reduce<<<(IDX4 + CRB - 1) / CRB, CRB>>>();   // 10 blocks
    finalize<<<1, BNT>>>((float*)d_out, bw, bb);
}